// round 2
// baseline (speedup 1.0000x reference)
#include <cuda_runtime.h>
#include <cstdint>

#define B_N 65536
#define X_N 362
#define GRID_S 19
#define TB 256

typedef unsigned long long u64;

// ---- scratch (static device globals; no runtime allocation) ----
__device__ int   g_cnt[3];
__device__ int   g_meta[3 * B_N];        // row | (ptr<<16)
__device__ float g_att[3 * B_N * 6];     // gathered 6-vector per bucketed sample

// ---- packed fp32x2 helpers (FFMA2: 2 fp32 MACs/lane/instr) ----
static __device__ __forceinline__ u64 pack2(float lo, float hi) {
    u64 r; asm("mov.b64 %0, {%1, %2};" : "=l"(r) : "f"(lo), "f"(hi)); return r;
}
static __device__ __forceinline__ void unpack2(u64 v, float &lo, float &hi) {
    asm("mov.b64 {%0, %1}, %2;" : "=f"(lo), "=f"(hi) : "l"(v));
}
static __device__ __forceinline__ void fma2(u64 &d, u64 a, u64 b) {
    asm("fma.rn.f32x2 %0, %1, %2, %0;" : "+l"(d) : "l"(a), "l"(b));
}
static __device__ __forceinline__ u64 ld64(const float *p) {
    return *reinterpret_cast<const u64 *>(p);
}

// ---- K0: reset bucket counters ----
__global__ void __launch_bounds__(32) zero_kernel() {
    if (threadIdx.x < 3) g_cnt[threadIdx.x] = 0;
}

// ---- K1: copy out=x, argmax, gather att, bucket by action ----
__global__ void __launch_bounds__(1024) prep_kernel(const float *__restrict__ x,
                                                    const int *__restrict__ act,
                                                    float *__restrict__ out) {
    __shared__ int   s_cnt[3], s_base[3];
    __shared__ int   s_a[32], s_slot[32], s_meta[32];
    __shared__ float s_att[32][6];

    int tid = threadIdx.x, lane = tid & 31, w = tid >> 5;
    if (tid < 3) s_cnt[tid] = 0;
    __syncthreads();

    int row = blockIdx.x * 32 + w;
    const float2 *xr   = reinterpret_cast<const float2 *>(x + (size_t)row * X_N);
    float2       *orow = reinterpret_cast<float2 *>(out + (size_t)row * X_N);

    float bv = -3.4e38f;
    int   bi = 0;
    for (int pi = lane; pi < X_N / 2; pi += 32) {   // 362 = 181 float2, streaming copy+argmax
        float2 v = xr[pi];
        orow[pi] = v;
        if (v.x > bv) { bv = v.x; bi = 2 * pi; }
        if (v.y > bv) { bv = v.y; bi = 2 * pi + 1; }
    }
#pragma unroll
    for (int off = 16; off > 0; off >>= 1) {        // argmax reduce, first-index on ties
        float ov = __shfl_down_sync(0xffffffffu, bv, off);
        int   oi = __shfl_down_sync(0xffffffffu, bi, off);
        if (ov > bv || (ov == bv && oi < bi)) { bv = ov; bi = oi; }
    }

    if (lane == 0) {
        int ptr = bi;
        int a   = act[row];
        const float *xp = x + (size_t)row * X_N;
        int il  = min(max(ptr - GRID_S, 1), X_N - 1);
        int ir  = min(max(ptr + GRID_S, 1), X_N - 1);
        int iu  = min(max(ptr - 1, 1), X_N - 1);
        int idn = min(max(ptr + 1, 1), X_N - 1);
        s_att[w][0] = xp[0];
        s_att[w][1] = bv;       // xp[ptr]
        s_att[w][2] = xp[il];
        s_att[w][3] = xp[ir];
        s_att[w][4] = xp[iu];
        s_att[w][5] = xp[idn];
        s_meta[w] = row | (ptr << 16);
        s_a[w]    = a;
        s_slot[w] = atomicAdd(&s_cnt[a], 1);
    }
    __syncthreads();
    if (tid < 3) s_base[tid] = atomicAdd(&g_cnt[tid], s_cnt[tid]);  // 3 global atomics/CTA
    __syncthreads();
    if (lane == 0) {
        int a = s_a[w];
        int g = s_base[a] + s_slot[w];
        g_meta[a * B_N + g] = s_meta[w];
        float *dst = &g_att[(size_t)(a * B_N + g) * 6];
#pragma unroll
        for (int j = 0; j < 6; j++) dst[j] = s_att[w][j];
    }
}

// ---- K2: per-bucket tiled MLP (64 samples/CTA, one action) + scatter ----
__global__ void __launch_bounds__(TB, 1) mlp_kernel(
    const float *__restrict__ W1, const float *__restrict__ b1,
    const float *__restrict__ W2, const float *__restrict__ b2,
    const float *__restrict__ W3, const float *__restrict__ b3,
    const float *__restrict__ W4, const float *__restrict__ b4,
    float *__restrict__ out) {
    // resolve (action, tile) from bucket counts written by K1
    int c0 = g_cnt[0], c1 = g_cnt[1], c2 = g_cnt[2];
    int t0 = (c0 + 63) >> 6, t1 = (c1 + 63) >> 6, t2 = (c2 + 63) >> 6;
    int bid = blockIdx.x;
    int a, tile, cnt;
    if (bid < t0)                { a = 0; tile = bid;            cnt = c0; }
    else if (bid < t0 + t1)      { a = 1; tile = bid - t0;       cnt = c1; }
    else if (bid < t0 + t1 + t2) { a = 2; tile = bid - t0 - t1;  cnt = c2; }
    else return;
    int base = tile * 64;
    int nv   = min(64, cnt - base);

    extern __shared__ float sm[];
    float *att_s = sm;                          // 64*6   = 384
    float *h13   = sm + 384;                    // 64*100 = 6400  (h1, later reused for h3)
    float *h2s   = sm + 384 + 6400;             // 64*400 = 25600
    float *w4s   = sm + 384 + 6400 + 25600;     // 600
    float *b4s   = w4s + 600;                   // 6
    __shared__ int meta_s[64];

    int tid = threadIdx.x;

    // cooperative loads (out-of-range lanes write zeros, never touch scratch)
    for (int t = tid; t < 384; t += TB) {
        int s = t / 6;
        att_s[t] = (s < nv) ? g_att[(size_t)(a * B_N + base) * 6 + t] : 0.f;
    }
    if (tid < 64) meta_s[tid] = (tid < nv) ? g_meta[a * B_N + base + tid] : 0;
    for (int t = tid; t < 600; t += TB) w4s[t] = W4[a * 600 + t];
    if (tid < 6) b4s[tid] = b4[a * 6 + tid];
    __syncthreads();

    // ---- layer 1: h1[64][100] ----
    const float *W1a = W1 + a * 600;
    const float *b1a = b1 + a * 100;
    for (int t = tid; t < 6400; t += TB) {
        int s = t / 100, j = t - s * 100;
        float acc = b1a[j];
        const float *as = att_s + s * 6;
#pragma unroll
        for (int k = 0; k < 6; k++) acc = fmaf(as[k], W1a[k * 100 + j], acc);
        h13[t] = fmaxf(acc, 0.f);
    }
    __syncthreads();

    int xl = tid & 31;
    int ty = tid >> 5;     // warp id 0..7 -> owns samples s0..s0+7
    int s0 = ty * 8;

    // ---- layer 2: h2[64][400] = relu(h1 @ W2 + b2), two 256-wide n-tiles ----
    const float *W2a = W2 + a * 40000;
    const float *b2a = b2 + a * 400;
    for (int n0 = 0; n0 < 512; n0 += 256) {
        int nb = n0 + 2 * xl;
        u64 acc[8][4];
        u64 bb[4];
#pragma unroll
        for (int rr = 0; rr < 4; rr++) {
            int n = nb + 64 * rr;
            bb[rr] = (n < 400) ? ld64(b2a + n) : 0ull;
        }
#pragma unroll
        for (int m = 0; m < 8; m++)
#pragma unroll
            for (int rr = 0; rr < 4; rr++) acc[m][rr] = bb[rr];

#pragma unroll 2
        for (int k = 0; k < 100; k++) {
            u64 wv[4];
            const float *wr = W2a + k * 400 + nb;
#pragma unroll
            for (int rr = 0; rr < 4; rr++) {
                int n = nb + 64 * rr;
                wv[rr] = (n < 400) ? ld64(wr + 64 * rr) : 0ull;    // coalesced 8B
            }
            u64 av[8];
#pragma unroll
            for (int m = 0; m < 8; m++) {
                float v = h13[(s0 + m) * 100 + k];                 // LDS broadcast
                av[m] = pack2(v, v);
            }
#pragma unroll
            for (int m = 0; m < 8; m++)
#pragma unroll
                for (int rr = 0; rr < 4; rr++) fma2(acc[m][rr], av[m], wv[rr]);
        }
#pragma unroll
        for (int m = 0; m < 8; m++)
#pragma unroll
            for (int rr = 0; rr < 4; rr++) {
                int n = nb + 64 * rr;
                if (n < 400) {
                    float lo, hi; unpack2(acc[m][rr], lo, hi);
                    *reinterpret_cast<float2 *>(&h2s[(s0 + m) * 400 + n]) =
                        make_float2(fmaxf(lo, 0.f), fmaxf(hi, 0.f));
                }
            }
    }
    __syncwarp();   // each warp's h1/h2/h3 rows are private to it

    // ---- layer 3: h3[64][100] = relu(h2 @ W3 + b3) (compute padded to 128) ----
    const float *W3a = W3 + a * 40000;
    const float *b3a = b3 + a * 100;
    {
        int nb = 2 * xl;
        u64 acc[8][2];
        u64 bb[2];
#pragma unroll
        for (int rr = 0; rr < 2; rr++) {
            int n = nb + 64 * rr;
            bb[rr] = (n < 100) ? ld64(b3a + n) : 0ull;
        }
#pragma unroll
        for (int m = 0; m < 8; m++)
#pragma unroll
            for (int rr = 0; rr < 2; rr++) acc[m][rr] = bb[rr];

#pragma unroll 2
        for (int k = 0; k < 400; k++) {
            u64 wv[2];
            const float *wr = W3a + k * 100 + nb;
#pragma unroll
            for (int rr = 0; rr < 2; rr++) {
                int n = nb + 64 * rr;
                wv[rr] = (n < 100) ? ld64(wr + 64 * rr) : 0ull;
            }
            u64 av[8];
#pragma unroll
            for (int m = 0; m < 8; m++) {
                float v = h2s[(s0 + m) * 400 + k];                 // LDS broadcast
                av[m] = pack2(v, v);
            }
#pragma unroll
            for (int m = 0; m < 8; m++)
#pragma unroll
                for (int rr = 0; rr < 2; rr++) fma2(acc[m][rr], av[m], wv[rr]);
        }
#pragma unroll
        for (int m = 0; m < 8; m++)
#pragma unroll
            for (int rr = 0; rr < 2; rr++) {
                int n = nb + 64 * rr;
                if (n < 100) {
                    float lo, hi; unpack2(acc[m][rr], lo, hi);
                    *reinterpret_cast<float2 *>(&h13[(s0 + m) * 100 + n]) =
                        make_float2(fmaxf(lo, 0.f), fmaxf(hi, 0.f));
                }
            }
    }
    __syncthreads();

    // ---- layer 4 + ordered last-wins scatter ----
    if (tid < nv) {
        int s = tid;
        float p0 = b4s[0], p1 = b4s[1], p2 = b4s[2], p3 = b4s[3], p4 = b4s[4], p5 = b4s[5];
        const float *hr = h13 + s * 100;
        for (int k = 0; k < 100; k++) {
            float v = hr[k];
            const float *wk = w4s + k * 6;
            p0 = fmaf(v, wk[0], p0);
            p1 = fmaf(v, wk[1], p1);
            p2 = fmaf(v, wk[2], p2);
            p3 = fmaf(v, wk[3], p3);
            p4 = fmaf(v, wk[4], p4);
            p5 = fmaf(v, wk[5], p5);
        }
        int meta = meta_s[s];
        int row  = meta & 0xFFFF;
        int ptr  = meta >> 16;
        float *orow = out + (size_t)row * X_N;
        float pr[6] = {p0, p1, p2, p3, p4, p5};
        int idx[6];
        idx[0] = 0;
        idx[1] = ptr;
        idx[2] = min(max(ptr - GRID_S, 1), X_N - 1);
        idx[3] = min(max(ptr + GRID_S, 1), X_N - 1);
        idx[4] = min(max(ptr - 1, 1), X_N - 1);
        idx[5] = min(max(ptr + 1, 1), X_N - 1);
        // program order within one thread => duplicate indices resolve last-wins,
        // matching the reference's sequential .set() loop. out[idx]=att+pred.
#pragma unroll
        for (int j = 0; j < 6; j++) orow[idx[j]] = att_s[s * 6 + j] + pr[j];
    }
}

// ---- launcher ----
extern "C" void kernel_launch(void *const *d_in, const int *in_sizes, int n_in,
                              void *d_out, int out_size) {
    const float *x  = (const float *)d_in[0];
    const float *W1 = (const float *)d_in[1];
    const float *b1 = (const float *)d_in[2];
    const float *W2 = (const float *)d_in[3];
    const float *b2 = (const float *)d_in[4];
    const float *W3 = (const float *)d_in[5];
    const float *b3 = (const float *)d_in[6];
    const float *W4 = (const float *)d_in[7];
    const float *b4 = (const float *)d_in[8];
    const int   *act = (const int *)d_in[9];
    float *out = (float *)d_out;

    size_t smem = (size_t)(384 + 6400 + 25600 + 600 + 6) * sizeof(float);  // ~129 KB
    cudaFuncSetAttribute(mlp_kernel, cudaFuncAttributeMaxDynamicSharedMemorySize, (int)smem);

    zero_kernel<<<1, 32>>>();
    prep_kernel<<<B_N / 32, 1024>>>(x, act, out);
    // worst case sum of per-action tile counts: 1024 + 2
    mlp_kernel<<<1026, TB, smem>>>(W1, b1, W2, b2, W3, b3, W4, b4, out);
}

// round 3
// speedup vs baseline: 1.5457x; 1.5457x over previous
#include <cuda_runtime.h>
#include <cstdint>

#define B_N 65536
#define X_N 362
#define GRID_S 19

typedef unsigned long long u64;

// ---- scratch (static device globals; no runtime allocation) ----
__device__ int   g_cnt[3];
__device__ int   g_meta[3 * B_N];          // row | (ptr<<16)
__device__ float g_att[3 * B_N * 6];       // gathered 6-vector per bucketed sample
__device__ float2 g_w2i[3 * 50 * 400];     // W2 k-pair interleaved: [a][kp][n] = (W2[2kp][n], W2[2kp+1][n])
__device__ float2 g_w3i[3 * 200 * 128];    // W3 k-pair interleaved, n padded 100->128 with zeros

// ---- packed fp32x2 helpers ----
static __device__ __forceinline__ u64 pack2(float lo, float hi) {
    u64 r; asm("mov.b64 %0, {%1, %2};" : "=l"(r) : "f"(lo), "f"(hi)); return r;
}
static __device__ __forceinline__ void unpack2(u64 v, float &lo, float &hi) {
    asm("mov.b64 {%0, %1}, %2;" : "=f"(lo), "=f"(hi) : "l"(v));
}
static __device__ __forceinline__ void fma2(u64 &d, u64 a, u64 b) {
    asm("fma.rn.f32x2 %0, %1, %2, %0;" : "+l"(d) : "l"(a), "l"(b));
}
static __device__ __forceinline__ u64 ld64(const float *p) {
    return *reinterpret_cast<const u64 *>(p);
}

// ---- K0: build k-interleaved weights + reset bucket counters ----
// 60000 elems for w2i, 76800 for w3i
__global__ void __launch_bounds__(256) wprep_kernel(const float *__restrict__ W2,
                                                    const float *__restrict__ W3) {
    if (blockIdx.x == 0 && threadIdx.x < 3) g_cnt[threadIdx.x] = 0;
    int idx = blockIdx.x * 256 + threadIdx.x;
    if (idx < 60000) {
        int a = idx / 20000, r = idx % 20000;
        int kp = r / 400, n = r % 400;
        const float *w = W2 + a * 40000 + (2 * kp) * 400 + n;
        g_w2i[idx] = make_float2(w[0], w[400]);
    } else if (idx < 60000 + 76800) {
        int i2 = idx - 60000;
        int a = i2 / 25600, r = i2 % 25600;
        int kp = r / 128, n = r % 128;
        float2 v = make_float2(0.f, 0.f);
        if (n < 100) {
            const float *w = W3 + a * 40000 + (2 * kp) * 100 + n;
            v = make_float2(w[0], w[100]);
        }
        g_w3i[i2] = v;
    }
}

// ---- K1: copy out=x, argmax, gather att, bucket by action ----
__global__ void __launch_bounds__(1024) prep_kernel(const float *__restrict__ x,
                                                    const int *__restrict__ act,
                                                    float *__restrict__ out) {
    __shared__ int   s_cnt[3], s_base[3];
    __shared__ int   s_a[32], s_slot[32], s_meta[32];
    __shared__ float s_att[32][6];

    int tid = threadIdx.x, lane = tid & 31, w = tid >> 5;
    if (tid < 3) s_cnt[tid] = 0;
    __syncthreads();

    int row = blockIdx.x * 32 + w;
    const float2 *xr   = reinterpret_cast<const float2 *>(x + (size_t)row * X_N);
    float2       *orow = reinterpret_cast<float2 *>(out + (size_t)row * X_N);

    float bv = -3.4e38f;
    int   bi = 0;
    for (int pi = lane; pi < X_N / 2; pi += 32) {   // 362 = 181 float2
        float2 v = xr[pi];
        orow[pi] = v;
        if (v.x > bv) { bv = v.x; bi = 2 * pi; }
        if (v.y > bv) { bv = v.y; bi = 2 * pi + 1; }
    }
#pragma unroll
    for (int off = 16; off > 0; off >>= 1) {        // argmax, first index on ties
        float ov = __shfl_down_sync(0xffffffffu, bv, off);
        int   oi = __shfl_down_sync(0xffffffffu, bi, off);
        if (ov > bv || (ov == bv && oi < bi)) { bv = ov; bi = oi; }
    }

    if (lane == 0) {
        int ptr = bi;
        int a   = act[row];
        const float *xp = x + (size_t)row * X_N;
        int il  = min(max(ptr - GRID_S, 1), X_N - 1);
        int ir  = min(max(ptr + GRID_S, 1), X_N - 1);
        int iu  = min(max(ptr - 1, 1), X_N - 1);
        int idn = min(max(ptr + 1, 1), X_N - 1);
        s_att[w][0] = xp[0];
        s_att[w][1] = bv;
        s_att[w][2] = xp[il];
        s_att[w][3] = xp[ir];
        s_att[w][4] = xp[iu];
        s_att[w][5] = xp[idn];
        s_meta[w] = row | (ptr << 16);
        s_a[w]    = a;
        s_slot[w] = atomicAdd(&s_cnt[a], 1);
    }
    __syncthreads();
    if (tid < 3) s_base[tid] = atomicAdd(&g_cnt[tid], s_cnt[tid]);
    __syncthreads();
    if (lane == 0) {
        int a = s_a[w];
        int g = s_base[a] + s_slot[w];
        g_meta[a * B_N + g] = s_meta[w];
        float *dst = &g_att[(size_t)(a * B_N + g) * 6];
#pragma unroll
        for (int j = 0; j < 6; j++) dst[j] = s_att[w][j];
    }
}

// ---- K2: per-bucket tiled MLP, 64 samples/CTA, 512 threads, k-split f32x2 ----
__global__ void __launch_bounds__(512, 1) mlp_kernel(
    const float *__restrict__ W1, const float *__restrict__ b1,
    const float *__restrict__ b2, const float *__restrict__ b3,
    const float *__restrict__ W4, const float *__restrict__ b4,
    float *__restrict__ out) {
    int c0 = g_cnt[0], c1 = g_cnt[1], c2 = g_cnt[2];
    int t0 = (c0 + 63) >> 6, t1 = (c1 + 63) >> 6, t2 = (c2 + 63) >> 6;
    int bid = blockIdx.x;
    int a, tile, cnt;
    if (bid < t0)                { a = 0; tile = bid;            cnt = c0; }
    else if (bid < t0 + t1)      { a = 1; tile = bid - t0;       cnt = c1; }
    else if (bid < t0 + t1 + t2) { a = 2; tile = bid - t0 - t1;  cnt = c2; }
    else return;
    int base = tile * 64;
    int nv   = min(64, cnt - base);

    extern __shared__ float sm[];
    float *att_s = sm;                              // 64*6   = 384
    float *h13   = sm + 384;                        // 64*100 = 6400 (h1 then h3)
    float *h2s   = sm + 384 + 6400;                 // 64*400 = 25600
    float *w4s   = sm + 384 + 6400 + 25600;         // 600
    float *w1s   = w4s + 600;                       // 600
    float *b1s   = w1s + 600;                       // 100
    float *b4s   = b1s + 100;                       // 6
    __shared__ int meta_s[64];

    int tid = threadIdx.x;

    // cooperative loads
    for (int t = tid; t < 384; t += 512) {
        int s = t / 6;
        att_s[t] = (s < nv) ? g_att[(size_t)(a * B_N + base) * 6 + t] : 0.f;
    }
    if (tid < 64) meta_s[tid] = (tid < nv) ? g_meta[a * B_N + base + tid] : 0;
    for (int t = tid; t < 600; t += 512) {
        w4s[t] = W4[a * 600 + t];
        w1s[t] = W1[a * 600 + t];
    }
    if (tid < 100) b1s[tid] = b1[a * 100 + tid];
    if (tid >= 128 && tid < 134) b4s[tid - 128] = b4[a * 6 + (tid - 128)];
    __syncthreads();

    // ---- layer 1: h1[64][100] ----
    for (int t = tid; t < 6400; t += 512) {
        int s = t / 100, j = t - s * 100;
        float acc = b1s[j];
        const float *as = att_s + s * 6;
#pragma unroll
        for (int k = 0; k < 6; k++) acc = fmaf(as[k], w1s[k * 100 + j], acc);
        h13[t] = fmaxf(acc, 0.f);
    }
    __syncthreads();

    int xl = tid & 31;
    int wp = tid >> 5;      // warp 0..15 owns samples s0..s0+3
    int s0 = wp * 4;

    // ---- layer 2: h2[64][400], k-split f32x2, two n-tiles [0,256) and [144,400) ----
    const u64 *W2i = reinterpret_cast<const u64 *>(g_w2i) + a * 20000;  // [kp][n], row 400
    const float *b2a = b2 + a * 400;
#pragma unroll 1
    for (int tb = 0; tb <= 144; tb += 144) {
        int nbase = tb + xl;
        u64 acc[4][8];
#pragma unroll
        for (int j = 0; j < 8; j++) {
            u64 ini = pack2(b2a[nbase + 32 * j], 0.f);
#pragma unroll
            for (int m = 0; m < 4; m++) acc[m][j] = ini;
        }
#pragma unroll 2
        for (int kp = 0; kp < 50; kp++) {
            u64 wv[8];
            const u64 *wr = W2i + kp * 400 + nbase;
#pragma unroll
            for (int j = 0; j < 8; j++) wv[j] = wr[32 * j];        // coalesced 8B
            u64 av[4];
#pragma unroll
            for (int m = 0; m < 4; m++) av[m] = ld64(&h13[(s0 + m) * 100 + 2 * kp]);  // LDS.64 bcast
#pragma unroll
            for (int m = 0; m < 4; m++)
#pragma unroll
                for (int j = 0; j < 8; j++) fma2(acc[m][j], av[m], wv[j]);
        }
#pragma unroll
        for (int m = 0; m < 4; m++)
#pragma unroll
            for (int j = 0; j < 8; j++) {
                float lo, hi; unpack2(acc[m][j], lo, hi);
                h2s[(s0 + m) * 400 + nbase + 32 * j] = fmaxf(lo + hi, 0.f);
            }
    }
    __syncwarp();   // h1/h2/h3 rows are warp-private

    // ---- layer 3: h3[64][100], k-split f32x2, single 128-wide padded tile ----
    const u64 *W3i = reinterpret_cast<const u64 *>(g_w3i) + a * 25600;  // [kp][n], row 128
    const float *b3a = b3 + a * 100;
    {
        u64 acc[4][4];
#pragma unroll
        for (int j = 0; j < 4; j++) {
            int n = xl + 32 * j;
            u64 ini = pack2((n < 100) ? b3a[n] : 0.f, 0.f);
#pragma unroll
            for (int m = 0; m < 4; m++) acc[m][j] = ini;
        }
#pragma unroll 2
        for (int kp = 0; kp < 200; kp++) {
            u64 wv[4];
            const u64 *wr = W3i + kp * 128 + xl;
#pragma unroll
            for (int j = 0; j < 4; j++) wv[j] = wr[32 * j];
            u64 av[4];
#pragma unroll
            for (int m = 0; m < 4; m++) av[m] = ld64(&h2s[(s0 + m) * 400 + 2 * kp]);
#pragma unroll
            for (int m = 0; m < 4; m++)
#pragma unroll
                for (int j = 0; j < 4; j++) fma2(acc[m][j], av[m], wv[j]);
        }
#pragma unroll
        for (int m = 0; m < 4; m++)
#pragma unroll
            for (int j = 0; j < 4; j++) {
                int n = xl + 32 * j;
                if (n < 100) {
                    float lo, hi; unpack2(acc[m][j], lo, hi);
                    h13[(s0 + m) * 100 + n] = fmaxf(lo + hi, 0.f);
                }
            }
    }
    __syncthreads();

    // ---- layer 4 + ordered last-wins scatter ----
    if (tid < nv) {
        int s = tid;
        float p0 = b4s[0], p1 = b4s[1], p2 = b4s[2], p3 = b4s[3], p4 = b4s[4], p5 = b4s[5];
        const float *hr = h13 + s * 100;
        for (int k = 0; k < 100; k++) {
            float v = hr[k];
            const float *wk = w4s + k * 6;
            p0 = fmaf(v, wk[0], p0);
            p1 = fmaf(v, wk[1], p1);
            p2 = fmaf(v, wk[2], p2);
            p3 = fmaf(v, wk[3], p3);
            p4 = fmaf(v, wk[4], p4);
            p5 = fmaf(v, wk[5], p5);
        }
        int meta = meta_s[s];
        int row  = meta & 0xFFFF;
        int ptr  = meta >> 16;
        float *orow = out + (size_t)row * X_N;
        float pr[6] = {p0, p1, p2, p3, p4, p5};
        int idx[6];
        idx[0] = 0;
        idx[1] = ptr;
        idx[2] = min(max(ptr - GRID_S, 1), X_N - 1);
        idx[3] = min(max(ptr + GRID_S, 1), X_N - 1);
        idx[4] = min(max(ptr - 1, 1), X_N - 1);
        idx[5] = min(max(ptr + 1, 1), X_N - 1);
        // program order within one thread => last-wins like reference loop
#pragma unroll
        for (int j = 0; j < 6; j++) orow[idx[j]] = att_s[s * 6 + j] + pr[j];
    }
}

// ---- launcher ----
extern "C" void kernel_launch(void *const *d_in, const int *in_sizes, int n_in,
                              void *d_out, int out_size) {
    const float *x  = (const float *)d_in[0];
    const float *W1 = (const float *)d_in[1];
    const float *b1 = (const float *)d_in[2];
    const float *W2 = (const float *)d_in[3];
    const float *b2 = (const float *)d_in[4];
    const float *W3 = (const float *)d_in[5];
    const float *b3 = (const float *)d_in[6];
    const float *W4 = (const float *)d_in[7];
    const float *b4 = (const float *)d_in[8];
    const int   *act = (const int *)d_in[9];
    float *out = (float *)d_out;

    size_t smem = (size_t)(384 + 6400 + 25600 + 600 + 600 + 100 + 6) * sizeof(float);  // ~132 KB
    cudaFuncSetAttribute(mlp_kernel, cudaFuncAttributeMaxDynamicSharedMemorySize, (int)smem);

    wprep_kernel<<<(60000 + 76800 + 255) / 256, 256>>>(W2, W3);
    prep_kernel<<<B_N / 32, 1024>>>(x, act, out);
    mlp_kernel<<<1026, 512, smem>>>(W1, b1, b2, b3, W4, b4, out);
}

// round 5
// speedup vs baseline: 5.9268x; 3.8345x over previous
#include <cuda_runtime.h>
#include <cuda_bf16.h>
#include <cstdint>

#define B_N 65536
#define X_N 362
#define GRID_S 19

// mma tiling: layer2 D[128x400]=h1[128x112]@W2t, layer3 D[128x112]=h2[128x400]@W3t
#define NT2 50
#define KT2 7
#define NT3 14
#define KT3 25

// ---- K2 dynamic smem layout (bytes) ----
#define WF2_OFF  0            // W2 B-fragments: 7*50*32*2 u32 = 89600 B
#define WF3_OFF  89600        // W3 B-fragments: 25*14*32*2 u32 = 89600 B
#define ATT_OFF  179200       // 128*6 f32
#define META_OFF 182272       // 128 int
#define W1S_OFF  182784       // 600 f32
#define B1S_OFF  185184       // 100 f32
#define W4S_OFF  185584       // 600 f32
#define B2S_OFF  187984       // 400 f32
#define B3S_OFF  189584       // 100 f32
#define B4S_OFF  189984       // 6 f32
#define SMEM_SZ  190016

// ---- scratch (static device globals; no runtime allocation) ----
__device__ int      g_cnt[3];
__device__ int      g_meta[3 * B_N];
__device__ float    g_att[3 * B_N * 6];
__device__ uint32_t g_w2f[3 * KT2 * NT2 * 64];   // [a][kt][nt][lane][2] bf16x2 B-fragments
__device__ uint32_t g_w3f[3 * KT3 * NT3 * 64];

// ---- helpers ----
static __device__ __forceinline__ uint32_t cvt_bf16x2(float lo, float hi) {
    uint32_t r;
    asm("cvt.rn.bf16x2.f32 %0, %1, %2;" : "=r"(r) : "f"(hi), "f"(lo));   // low half = lo
    return r;
}
static __device__ __forceinline__ void mma16816(float *c, const uint32_t *a,
                                                uint32_t b0, uint32_t b1) {
    asm volatile(
        "mma.sync.aligned.m16n8k16.row.col.f32.bf16.bf16.f32 "
        "{%0,%1,%2,%3}, {%4,%5,%6,%7}, {%8,%9}, {%0,%1,%2,%3};"
        : "+f"(c[0]), "+f"(c[1]), "+f"(c[2]), "+f"(c[3])
        : "r"(a[0]), "r"(a[1]), "r"(a[2]), "r"(a[3]), "r"(b0), "r"(b1));
}

// ---- K0: build B-fragment weight images (zero-padded) + reset counters ----
// B fragment (m16n8k16): lane=gid*4+tp holds b0=(B[k0+tp*2][n],B[k0+tp*2+1][n]),
// b1 = same at k+8, with n = nt*8+gid.
__global__ void __launch_bounds__(256) wprep_kernel(const float *__restrict__ W2,
                                                    const float *__restrict__ W3) {
    if (blockIdx.x == 0 && threadIdx.x < 3) g_cnt[threadIdx.x] = 0;
    int idx = blockIdx.x * 256 + threadIdx.x;
    if (idx < 67200) {                       // 3 * 7*50*64
        int a = idx / 22400, r = idx % 22400;
        int kt = r / 3200, r2 = r % 3200;
        int nt = r2 / 64, r3 = r2 % 64;
        int lane = r3 >> 1, breg = r3 & 1;
        int gid = lane >> 2, tp = lane & 3;
        int n = nt * 8 + gid;                // < 400
        int k = kt * 16 + tp * 2 + breg * 8; // pad k>=100 with 0
        float v0 = (k < 100) ? W2[a * 40000 + k * 400 + n] : 0.f;
        float v1 = (k + 1 < 100) ? W2[a * 40000 + (k + 1) * 400 + n] : 0.f;
        g_w2f[idx] = cvt_bf16x2(v0, v1);
    } else if (idx < 134400) {               // 3 * 25*14*64
        int i2 = idx - 67200;
        int a = i2 / 22400, r = i2 % 22400;
        int kt = r / 896, r2 = r % 896;
        int nt = r2 / 64, r3 = r2 % 64;
        int lane = r3 >> 1, breg = r3 & 1;
        int gid = lane >> 2, tp = lane & 3;
        int n = nt * 8 + gid;                // pad n>=100 with 0
        int k = kt * 16 + tp * 2 + breg * 8; // < 400 always
        float v0 = (n < 100) ? W3[a * 40000 + k * 100 + n] : 0.f;
        float v1 = (n < 100) ? W3[a * 40000 + (k + 1) * 100 + n] : 0.f;
        g_w3f[i2] = cvt_bf16x2(v0, v1);
    }
}

// ---- K1: copy out=x, argmax, gather att, bucket by action ----
__global__ void __launch_bounds__(1024) prep_kernel(const float *__restrict__ x,
                                                    const int *__restrict__ act,
                                                    float *__restrict__ out) {
    __shared__ int   s_cnt[3], s_base[3];
    __shared__ int   s_a[32], s_slot[32], s_meta[32];
    __shared__ float s_att[32][6];

    int tid = threadIdx.x, lane = tid & 31, w = tid >> 5;
    if (tid < 3) s_cnt[tid] = 0;
    __syncthreads();

    int row = blockIdx.x * 32 + w;
    const float2 *xr   = reinterpret_cast<const float2 *>(x + (size_t)row * X_N);
    float2       *orow = reinterpret_cast<float2 *>(out + (size_t)row * X_N);

    float bv = -3.4e38f;
    int   bi = 0;
    for (int pi = lane; pi < X_N / 2; pi += 32) {
        float2 v = xr[pi];
        orow[pi] = v;
        if (v.x > bv) { bv = v.x; bi = 2 * pi; }
        if (v.y > bv) { bv = v.y; bi = 2 * pi + 1; }
    }
#pragma unroll
    for (int off = 16; off > 0; off >>= 1) {   // argmax, first index on ties
        float ov = __shfl_down_sync(0xffffffffu, bv, off);
        int   oi = __shfl_down_sync(0xffffffffu, bi, off);
        if (ov > bv || (ov == bv && oi < bi)) { bv = ov; bi = oi; }
    }

    if (lane == 0) {
        int ptr = bi;
        int a   = act[row];
        const float *xp = x + (size_t)row * X_N;
        int il  = min(max(ptr - GRID_S, 1), X_N - 1);
        int ir  = min(max(ptr + GRID_S, 1), X_N - 1);
        int iu  = min(max(ptr - 1, 1), X_N - 1);
        int idn = min(max(ptr + 1, 1), X_N - 1);
        s_att[w][0] = xp[0];
        s_att[w][1] = bv;
        s_att[w][2] = xp[il];
        s_att[w][3] = xp[ir];
        s_att[w][4] = xp[iu];
        s_att[w][5] = xp[idn];
        s_meta[w] = row | (ptr << 16);
        s_a[w]    = a;
        s_slot[w] = atomicAdd(&s_cnt[a], 1);
    }
    __syncthreads();
    if (tid < 3) s_base[tid] = atomicAdd(&g_cnt[tid], s_cnt[tid]);
    __syncthreads();
    if (lane == 0) {
        int a = s_a[w];
        int g = s_base[a] + s_slot[w];
        g_meta[a * B_N + g] = s_meta[w];
        float *dst = &g_att[(size_t)(a * B_N + g) * 6];
#pragma unroll
        for (int j = 0; j < 6; j++) dst[j] = s_att[w][j];
    }
}

// ---- K2: mma.sync MLP. 128 samples/CTA (one action), 8 warps, frag-resident ----
__global__ void __launch_bounds__(256) mlp_kernel(
    const float *__restrict__ W1, const float *__restrict__ b1,
    const float *__restrict__ b2, const float *__restrict__ b3,
    const float *__restrict__ W4, const float *__restrict__ b4,
    float *__restrict__ out) {
    int c0n = g_cnt[0], c1n = g_cnt[1], c2n = g_cnt[2];
    int t0 = (c0n + 127) >> 7, t1 = (c1n + 127) >> 7, t2 = (c2n + 127) >> 7;
    int bid = blockIdx.x;
    int a, tile, cnt;
    if (bid < t0)                { a = 0; tile = bid;            cnt = c0n; }
    else if (bid < t0 + t1)      { a = 1; tile = bid - t0;       cnt = c1n; }
    else if (bid < t0 + t1 + t2) { a = 2; tile = bid - t0 - t1;  cnt = c2n; }
    else return;
    int base = tile * 128;
    int nv   = min(128, cnt - base);

    extern __shared__ char smem[];
    uint32_t *wf2 = reinterpret_cast<uint32_t *>(smem + WF2_OFF);
    uint32_t *wf3 = reinterpret_cast<uint32_t *>(smem + WF3_OFF);
    float *att_s = reinterpret_cast<float *>(smem + ATT_OFF);
    int   *meta_s = reinterpret_cast<int *>(smem + META_OFF);
    float *w1s = reinterpret_cast<float *>(smem + W1S_OFF);
    float *b1s = reinterpret_cast<float *>(smem + B1S_OFF);
    float *w4s = reinterpret_cast<float *>(smem + W4S_OFF);
    float *b2s = reinterpret_cast<float *>(smem + B2S_OFF);
    float *b3s = reinterpret_cast<float *>(smem + B3S_OFF);
    float *b4s = reinterpret_cast<float *>(smem + B4S_OFF);

    int tid = threadIdx.x, lane = tid & 31, wid = tid >> 5;
    int gid = lane >> 2, tp = lane & 3;

    // ---- phase 0: cooperative loads ----
    for (int t = tid; t < 768; t += 256) {
        int s = t / 6;
        att_s[t] = (s < nv) ? g_att[(size_t)(a * B_N + base) * 6 + t] : 0.f;
    }
    if (tid < 128) meta_s[tid] = (tid < nv) ? g_meta[a * B_N + base + tid] : 0;
    for (int t = tid; t < 600; t += 256) { w1s[t] = W1[a * 600 + t]; w4s[t] = W4[a * 600 + t]; }
    if (tid < 100) { b1s[tid] = b1[a * 100 + tid]; b3s[tid] = b3[a * 100 + tid]; }
    for (int t = tid; t < 400; t += 256) b2s[t] = b2[a * 400 + t];
    if (tid < 6) b4s[tid] = b4[a * 6 + tid];
    {
        const uint4 *s2 = reinterpret_cast<const uint4 *>(g_w2f + a * 22400);
        uint4 *d2 = reinterpret_cast<uint4 *>(wf2);
        for (int i = tid; i < 5600; i += 256) d2[i] = s2[i];
        const uint4 *s3 = reinterpret_cast<const uint4 *>(g_w3f + a * 22400);
        uint4 *d3 = reinterpret_cast<uint4 *>(wf3);
        for (int i = tid; i < 5600; i += 256) d3[i] = s3[i];
    }
    __syncthreads();

    int mt = wid;
    int r0 = mt * 16 + gid, r1 = r0 + 8;

    // ---- layer 1: compute h1 directly into this thread's A-fragments ----
    float at0[6], at1[6];
#pragma unroll
    for (int j = 0; j < 6; j++) { at0[j] = att_s[r0 * 6 + j]; at1[j] = att_s[r1 * 6 + j]; }

    uint32_t a2[KT2][4];
#pragma unroll
    for (int kt = 0; kt < KT2; kt++) {
        float h0[4], h1v[4];
        int ks0 = kt * 16 + tp * 2;
#pragma unroll
        for (int q = 0; q < 4; q++) {
            int k = ks0 + (q >> 1) * 8 + (q & 1);    // ks0, ks0+1, ks0+8, ks0+9
            float v0 = 0.f, v1 = 0.f;
            if (k < 100) {
                float acc0 = b1s[k], acc1 = b1s[k];
#pragma unroll
                for (int j = 0; j < 6; j++) {
                    float wv = w1s[j * 100 + k];
                    acc0 = fmaf(at0[j], wv, acc0);
                    acc1 = fmaf(at1[j], wv, acc1);
                }
                v0 = fmaxf(acc0, 0.f);
                v1 = fmaxf(acc1, 0.f);
            }
            h0[q] = v0; h1v[q] = v1;
        }
        a2[kt][0] = cvt_bf16x2(h0[0], h0[1]);
        a2[kt][1] = cvt_bf16x2(h1v[0], h1v[1]);
        a2[kt][2] = cvt_bf16x2(h0[2], h0[3]);
        a2[kt][3] = cvt_bf16x2(h1v[2], h1v[3]);
    }

    // ---- layer 2: 50 n-tiles in 10 chunks of 5; D-frags convert into layer-3 A-frags ----
    uint32_t a3[KT3][4];
#pragma unroll
    for (int ch = 0; ch < 10; ch++) {
        float c[5][4];
#pragma unroll
        for (int i = 0; i < 5; i++) {
            int nt = ch * 5 + i;
            float2 bb = *reinterpret_cast<const float2 *>(b2s + nt * 8 + tp * 2);
            c[i][0] = bb.x; c[i][1] = bb.y; c[i][2] = bb.x; c[i][3] = bb.y;
        }
#pragma unroll
        for (int kt = 0; kt < KT2; kt++) {
#pragma unroll
            for (int i = 0; i < 5; i++) {
                int nt = ch * 5 + i;
                uint2 bf = *reinterpret_cast<const uint2 *>(wf2 + ((kt * NT2 + nt) * 32 + lane) * 2);
                mma16816(c[i], a2[kt], bf.x, bf.y);
            }
        }
#pragma unroll
        for (int i = 0; i < 5; i++) {
            int nt = ch * 5 + i;
            uint32_t w0 = cvt_bf16x2(fmaxf(c[i][0], 0.f), fmaxf(c[i][1], 0.f));
            uint32_t w1 = cvt_bf16x2(fmaxf(c[i][2], 0.f), fmaxf(c[i][3], 0.f));
            a3[nt >> 1][(nt & 1) * 2 + 0] = w0;
            a3[nt >> 1][(nt & 1) * 2 + 1] = w1;
        }
    }

    // ---- layer 3 + fused layer 4 partials ----
    float p0[6] = {0, 0, 0, 0, 0, 0}, p1[6] = {0, 0, 0, 0, 0, 0};
#pragma unroll
    for (int nt = 0; nt < NT3; nt++) {
        int n0 = nt * 8 + tp * 2;
        float c[4];
        c[0] = (n0 < 100) ? b3s[n0] : 0.f;
        c[1] = (n0 + 1 < 100) ? b3s[n0 + 1] : 0.f;
        c[2] = c[0]; c[3] = c[1];
#pragma unroll
        for (int kt = 0; kt < KT3; kt++) {
            uint2 bf = *reinterpret_cast<const uint2 *>(wf3 + ((kt * NT3 + nt) * 32 + lane) * 2);
            mma16816(c, a3[kt], bf.x, bf.y);
        }
        float v0 = fmaxf(c[0], 0.f), v1 = fmaxf(c[1], 0.f);
        float v2 = fmaxf(c[2], 0.f), v3 = fmaxf(c[3], 0.f);
        if (n0 < 100) {
            const float *w = w4s + n0 * 6;
#pragma unroll
            for (int j = 0; j < 6; j++) {
                p0[j] = fmaf(v0, w[j], p0[j]);
                p1[j] = fmaf(v2, w[j], p1[j]);
            }
        }
        if (n0 + 1 < 100) {
            const float *w = w4s + (n0 + 1) * 6;
#pragma unroll
            for (int j = 0; j < 6; j++) {
                p0[j] = fmaf(v1, w[j], p0[j]);
                p1[j] = fmaf(v3, w[j], p1[j]);
            }
        }
    }
    // reduce across the 4 tp lanes of each row group
#pragma unroll
    for (int j = 0; j < 6; j++) {
        p0[j] += __shfl_xor_sync(0xffffffffu, p0[j], 1);
        p0[j] += __shfl_xor_sync(0xffffffffu, p0[j], 2);
        p1[j] += __shfl_xor_sync(0xffffffffu, p1[j], 1);
        p1[j] += __shfl_xor_sync(0xffffffffu, p1[j], 2);
    }

    // ---- scatter (lanes tp==0 own rows r0 and r1) ----
    if (tp == 0) {
#pragma unroll
        for (int h = 0; h < 2; h++) {
            int s = h ? r1 : r0;
            float *pp = h ? p1 : p0;
            if (s < nv) {
                int meta = meta_s[s];
                int row  = meta & 0xFFFF;
                int ptr  = meta >> 16;
                float *orow = out + (size_t)row * X_N;
                int idx[6];
                idx[0] = 0;
                idx[1] = ptr;
                idx[2] = min(max(ptr - GRID_S, 1), X_N - 1);
                idx[3] = min(max(ptr + GRID_S, 1), X_N - 1);
                idx[4] = min(max(ptr - 1, 1), X_N - 1);
                idx[5] = min(max(ptr + 1, 1), X_N - 1);
                // program order within one thread => last-wins like reference loop
#pragma unroll
                for (int j = 0; j < 6; j++)
                    orow[idx[j]] = att_s[s * 6 + j] + (pp[j] + b4s[j]);
            }
        }
    }
}

// ---- launcher ----
extern "C" void kernel_launch(void *const *d_in, const int *in_sizes, int n_in,
                              void *d_out, int out_size) {
    const float *x  = (const float *)d_in[0];
    const float *W1 = (const float *)d_in[1];
    const float *b1 = (const float *)d_in[2];
    const float *W2 = (const float *)d_in[3];
    const float *b2 = (const float *)d_in[4];
    const float *W3 = (const float *)d_in[5];
    const float *b3 = (const float *)d_in[6];
    const float *W4 = (const float *)d_in[7];
    const float *b4 = (const float *)d_in[8];
    const int   *act = (const int *)d_in[9];
    float *out = (float *)d_out;

    cudaFuncSetAttribute(mlp_kernel, cudaFuncAttributeMaxDynamicSharedMemorySize, SMEM_SZ);

    wprep_kernel<<<(134400 + 255) / 256, 256>>>(W2, W3);
    prep_kernel<<<B_N / 32, 1024>>>(x, act, out);
    // worst-case tile count: 512 + 1 + 1
    mlp_kernel<<<514, 256, SMEM_SZ>>>(W1, b1, b2, b3, W4, b4, out);
}

// round 7
// speedup vs baseline: 7.3224x; 1.2355x over previous
#include <cuda_runtime.h>
#include <cuda_bf16.h>
#include <cstdint>

#define B_N 65536
#define X_N 362
#define GRID_S 19

// layer2: D[.x400] = h1[.x112] @ W2t ; layer3: D[.x112] = h2[.x400] @ W3t
#define KT2 7     // layer2 k-tiles (112/16)
#define KT3 25    // layer3 k-tiles (400/16) == layer2 nt-pairs
#define NP3 7     // layer3 nt-pairs (14/2)

// ---- K2 dynamic smem layout (bytes) ----
#define WF2_OFF  0            // [kt3(25)][kt2(7)][lane(32)]{u32 x4} = 89600 B
#define WF3_OFF  89600        // [kt3(25)][p(7)][lane(32)]{u32 x4}   = 89600 B
#define ATT_OFF  179200       // 256*6 f32
#define META_OFF 185344       // 256 int
#define W1S_OFF  186368       // 600 f32
#define B1S_OFF  188768       // 100 f32
#define W4S_OFF  189168       // 600 f32
#define B2S_OFF  191568       // 400 f32
#define B3S_OFF  193168       // 100 f32
#define B4S_OFF  193568       // 6 f32
#define SMEM_SZ  193600

// ---- scratch (static device globals; no runtime allocation) ----
__device__ int      g_cnt[3];
__device__ int      g_meta[3 * B_N];
__device__ float    g_att[3 * B_N * 6];
__device__ uint32_t g_w2f[3 * KT3 * KT2 * 128];   // uint4-packed nt-pair B fragments
__device__ uint32_t g_w3f[3 * KT3 * NP3 * 128];

// ---- helpers ----
static __device__ __forceinline__ uint32_t cvt_bf16x2(float lo, float hi) {
    uint32_t r;
    asm("cvt.rn.bf16x2.f32 %0, %1, %2;" : "=r"(r) : "f"(hi), "f"(lo));   // low half = lo
    return r;
}
static __device__ __forceinline__ void mma16816(float *c, const uint32_t *a,
                                                uint32_t b0, uint32_t b1) {
    asm volatile(
        "mma.sync.aligned.m16n8k16.row.col.f32.bf16.bf16.f32 "
        "{%0,%1,%2,%3}, {%4,%5,%6,%7}, {%8,%9}, {%0,%1,%2,%3};"
        : "+f"(c[0]), "+f"(c[1]), "+f"(c[2]), "+f"(c[3])
        : "r"(a[0]), "r"(a[1]), "r"(a[2]), "r"(a[3]), "r"(b0), "r"(b1));
}

// ---- K0: build uint4-packed B-fragment images (zero-padded) + reset counters ----
// Fragment element u (0..3): nt = 2*kt3 + (u>>1), breg = u&1;
//   n = nt*8 + gid; k = kt2*16 + tp*2 + breg*8; value = bf16x2(W[k][n], W[k+1][n])
__global__ void __launch_bounds__(256) wprep_kernel(const float *__restrict__ W2,
                                                    const float *__restrict__ W3) {
    if (blockIdx.x == 0 && threadIdx.x < 3) g_cnt[threadIdx.x] = 0;
    int idx = blockIdx.x * 256 + threadIdx.x;
    if (idx < 67200) {                       // 3 * 25*7*128
        int a = idx / 22400, r = idx % 22400;
        int kt3 = r / 896, r2 = r % 896;
        int kt2 = r2 / 128, r3 = r2 % 128;
        int lane = r3 >> 2, u = r3 & 3;
        int gid = lane >> 2, tp = lane & 3;
        int nt = 2 * kt3 + (u >> 1), breg = u & 1;
        int n = nt * 8 + gid;                 // < 400
        int k = kt2 * 16 + tp * 2 + breg * 8; // pad k>=100
        float v0 = (k < 100) ? W2[a * 40000 + k * 400 + n] : 0.f;
        float v1 = (k + 1 < 100) ? W2[a * 40000 + (k + 1) * 400 + n] : 0.f;
        g_w2f[idx] = cvt_bf16x2(v0, v1);
    } else if (idx < 134400) {               // 3 * 25*7*128
        int i2 = idx - 67200;
        int a = i2 / 22400, r = i2 % 22400;
        int kt3 = r / 896, r2 = r % 896;
        int p = r2 / 128, r3 = r2 % 128;
        int lane = r3 >> 2, u = r3 & 3;
        int gid = lane >> 2, tp = lane & 3;
        int nt3 = 2 * p + (u >> 1), breg = u & 1;
        int n = nt3 * 8 + gid;                // pad n>=100
        int k = kt3 * 16 + tp * 2 + breg * 8; // < 400
        float v0 = (n < 100) ? W3[a * 40000 + k * 100 + n] : 0.f;
        float v1 = (n < 100) ? W3[a * 40000 + (k + 1) * 100 + n] : 0.f;
        g_w3f[i2] = cvt_bf16x2(v0, v1);
    }
}

// ---- K1: copy out=x (streaming stores), argmax, gather att, bucket by action ----
__global__ void __launch_bounds__(1024) prep_kernel(const float *__restrict__ x,
                                                    const int *__restrict__ act,
                                                    float *__restrict__ out) {
    __shared__ int   s_cnt[3], s_base[3];
    __shared__ int   s_a[32], s_slot[32], s_meta[32];
    __shared__ float s_att[32][6];

    int tid = threadIdx.x, lane = tid & 31, w = tid >> 5;
    if (tid < 3) s_cnt[tid] = 0;
    __syncthreads();

    int row = blockIdx.x * 32 + w;
    const float2 *xr   = reinterpret_cast<const float2 *>(x + (size_t)row * X_N);
    float2       *orow = reinterpret_cast<float2 *>(out + (size_t)row * X_N);

    float bv = -3.4e38f;
    int   bi = 0;
    for (int pi = lane; pi < X_N / 2; pi += 32) {
        float2 v = xr[pi];
        __stcs(&orow[pi], v);                 // streaming store: write-once data
        if (v.x > bv) { bv = v.x; bi = 2 * pi; }
        if (v.y > bv) { bv = v.y; bi = 2 * pi + 1; }
    }
#pragma unroll
    for (int off = 16; off > 0; off >>= 1) {  // argmax, first index on ties
        float ov = __shfl_down_sync(0xffffffffu, bv, off);
        int   oi = __shfl_down_sync(0xffffffffu, bi, off);
        if (ov > bv || (ov == bv && oi < bi)) { bv = ov; bi = oi; }
    }

    if (lane == 0) {
        int ptr = bi;
        int a   = act[row];
        const float *xp = x + (size_t)row * X_N;
        int il  = min(max(ptr - GRID_S, 1), X_N - 1);
        int ir  = min(max(ptr + GRID_S, 1), X_N - 1);
        int iu  = min(max(ptr - 1, 1), X_N - 1);
        int idn = min(max(ptr + 1, 1), X_N - 1);
        s_att[w][0] = xp[0];
        s_att[w][1] = bv;
        s_att[w][2] = xp[il];
        s_att[w][3] = xp[ir];
        s_att[w][4] = xp[iu];
        s_att[w][5] = xp[idn];
        s_meta[w] = row | (ptr << 16);
        s_a[w]    = a;
        s_slot[w] = atomicAdd(&s_cnt[a], 1);
    }
    __syncthreads();
    if (tid < 3) s_base[tid] = atomicAdd(&g_cnt[tid], s_cnt[tid]);
    __syncthreads();
    if (lane == 0) {
        int a = s_a[w];
        int g = s_base[a] + s_slot[w];
        g_meta[a * B_N + g] = s_meta[w];
        float *dst = &g_att[(size_t)(a * B_N + g) * 6];
#pragma unroll
        for (int j = 0; j < 6; j++) dst[j] = s_att[w][j];
    }
}

// ---- K2: fused mma MLP. 256 samples/CTA, 8 warps x 2 m-tiles, layers 2+3 fused ----
__global__ void __launch_bounds__(256, 1) mlp_kernel(
    const float *__restrict__ W1, const float *__restrict__ b1,
    const float *__restrict__ b2, const float *__restrict__ b3,
    const float *__restrict__ W4, const float *__restrict__ b4,
    float *__restrict__ out) {
    int c0n = g_cnt[0], c1n = g_cnt[1], c2n = g_cnt[2];
    int t0 = (c0n + 255) >> 8, t1 = (c1n + 255) >> 8, t2 = (c2n + 255) >> 8;
    int bid = blockIdx.x;
    int a, tile, cnt;
    if (bid < t0)                { a = 0; tile = bid;            cnt = c0n; }
    else if (bid < t0 + t1)      { a = 1; tile = bid - t0;       cnt = c1n; }
    else if (bid < t0 + t1 + t2) { a = 2; tile = bid - t0 - t1;  cnt = c2n; }
    else return;
    int base = tile * 256;
    int nv   = min(256, cnt - base);

    extern __shared__ char smem[];
    const uint4 *wf2 = reinterpret_cast<const uint4 *>(smem + WF2_OFF);
    const uint4 *wf3 = reinterpret_cast<const uint4 *>(smem + WF3_OFF);
    float *att_s = reinterpret_cast<float *>(smem + ATT_OFF);
    int   *meta_s = reinterpret_cast<int *>(smem + META_OFF);
    float *w1s = reinterpret_cast<float *>(smem + W1S_OFF);
    float *b1s = reinterpret_cast<float *>(smem + B1S_OFF);
    float *w4s = reinterpret_cast<float *>(smem + W4S_OFF);
    float *b2s = reinterpret_cast<float *>(smem + B2S_OFF);
    float *b3s = reinterpret_cast<float *>(smem + B3S_OFF);
    float *b4s = reinterpret_cast<float *>(smem + B4S_OFF);

    int tid = threadIdx.x, lane = tid & 31, wid = tid >> 5;
    int gid = lane >> 2, tp = lane & 3;

    // ---- phase 0: cooperative loads ----
    for (int t = tid; t < 1536; t += 256) {
        int s = t / 6;
        att_s[t] = (s < nv) ? g_att[(size_t)(a * B_N + base) * 6 + t] : 0.f;
    }
    if (tid < 256) meta_s[tid] = (tid < nv) ? g_meta[a * B_N + base + tid] : 0;
    for (int t = tid; t < 600; t += 256) { w1s[t] = W1[a * 600 + t]; w4s[t] = W4[a * 600 + t]; }
    if (tid < 100) { b1s[tid] = b1[a * 100 + tid]; b3s[tid] = b3[a * 100 + tid]; }
    for (int t = tid; t < 400; t += 256) b2s[t] = b2[a * 400 + t];
    if (tid < 6) b4s[tid] = b4[a * 6 + tid];
    {
        const uint4 *s2 = reinterpret_cast<const uint4 *>(g_w2f + a * 22400);
        uint4 *d2 = reinterpret_cast<uint4 *>(smem + WF2_OFF);
        for (int i = tid; i < 5600; i += 256) d2[i] = s2[i];
        const uint4 *s3 = reinterpret_cast<const uint4 *>(g_w3f + a * 22400);
        uint4 *d3 = reinterpret_cast<uint4 *>(smem + WF3_OFF);
        for (int i = tid; i < 5600; i += 256) d3[i] = s3[i];
    }
    __syncthreads();

    // ---- layer 1: h1 directly into A-fragments for both m-tiles ----
    uint32_t a2[2][KT2][4];
#pragma unroll
    for (int t = 0; t < 2; t++) {
        int mt = wid * 2 + t;
        int r0 = mt * 16 + gid, r1 = r0 + 8;
        float at0[6], at1[6];
#pragma unroll
        for (int j = 0; j < 6; j++) { at0[j] = att_s[r0 * 6 + j]; at1[j] = att_s[r1 * 6 + j]; }
#pragma unroll
        for (int kt = 0; kt < KT2; kt++) {
            float h0[4], h1v[4];
            int ks0 = kt * 16 + tp * 2;
#pragma unroll
            for (int q = 0; q < 4; q++) {
                int k = ks0 + (q >> 1) * 8 + (q & 1);
                float v0 = 0.f, v1 = 0.f;
                if (k < 100) {
                    float acc0 = b1s[k], acc1 = b1s[k];
#pragma unroll
                    for (int j = 0; j < 6; j++) {
                        float wv = w1s[j * 100 + k];
                        acc0 = fmaf(at0[j], wv, acc0);
                        acc1 = fmaf(at1[j], wv, acc1);
                    }
                    v0 = fmaxf(acc0, 0.f);
                    v1 = fmaxf(acc1, 0.f);
                }
                h0[q] = v0; h1v[q] = v1;
            }
            a2[t][kt][0] = cvt_bf16x2(h0[0], h0[1]);
            a2[t][kt][1] = cvt_bf16x2(h1v[0], h1v[1]);
            a2[t][kt][2] = cvt_bf16x2(h0[2], h0[3]);
            a2[t][kt][3] = cvt_bf16x2(h1v[2], h1v[3]);
        }
    }

    // ---- fused layers 2+3: per kt3, compute layer2 nt-pair then feed 14 layer3 mmas ----
    float c3[2][14][4];
#pragma unroll
    for (int t = 0; t < 2; t++)
#pragma unroll
        for (int nt = 0; nt < 14; nt++) {
            int n0 = nt * 8 + tp * 2;
            float bl = (n0 < 100) ? b3s[n0] : 0.f;
            float bh = (n0 + 1 < 100) ? b3s[n0 + 1] : 0.f;
            c3[t][nt][0] = bl; c3[t][nt][1] = bh; c3[t][nt][2] = bl; c3[t][nt][3] = bh;
        }

#pragma unroll 1
    for (int kt3 = 0; kt3 < KT3; kt3++) {
        // layer2 D for nt0 = 2kt3, nt1 = 2kt3+1, both m-tiles
        float c2[2][2][4];
#pragma unroll
        for (int t = 0; t < 2; t++)
#pragma unroll
            for (int h = 0; h < 2; h++) {
                float2 bb = *reinterpret_cast<const float2 *>(b2s + (2 * kt3 + h) * 8 + tp * 2);
                c2[t][h][0] = bb.x; c2[t][h][1] = bb.y; c2[t][h][2] = bb.x; c2[t][h][3] = bb.y;
            }
#pragma unroll
        for (int kt2 = 0; kt2 < KT2; kt2++) {
            uint4 bf = wf2[(kt3 * KT2 + kt2) * 32 + lane];
            mma16816(c2[0][0], a2[0][kt2], bf.x, bf.y);
            mma16816(c2[0][1], a2[0][kt2], bf.z, bf.w);
            mma16816(c2[1][0], a2[1][kt2], bf.x, bf.y);
            mma16816(c2[1][1], a2[1][kt2], bf.z, bf.w);
        }
        // relu + convert: layer2 D-frag pair -> layer3 A-frag (kt = kt3)
        uint32_t a3f[2][4];
#pragma unroll
        for (int t = 0; t < 2; t++) {
            a3f[t][0] = cvt_bf16x2(fmaxf(c2[t][0][0], 0.f), fmaxf(c2[t][0][1], 0.f));
            a3f[t][1] = cvt_bf16x2(fmaxf(c2[t][0][2], 0.f), fmaxf(c2[t][0][3], 0.f));
            a3f[t][2] = cvt_bf16x2(fmaxf(c2[t][1][0], 0.f), fmaxf(c2[t][1][1], 0.f));
            a3f[t][3] = cvt_bf16x2(fmaxf(c2[t][1][2], 0.f), fmaxf(c2[t][1][3], 0.f));
        }
        // layer3 partial products for this kt3
#pragma unroll
        for (int p = 0; p < NP3; p++) {
            uint4 bf = wf3[(kt3 * NP3 + p) * 32 + lane];
            mma16816(c3[0][2 * p],     a3f[0], bf.x, bf.y);
            mma16816(c3[0][2 * p + 1], a3f[0], bf.z, bf.w);
            mma16816(c3[1][2 * p],     a3f[1], bf.x, bf.y);
            mma16816(c3[1][2 * p + 1], a3f[1], bf.z, bf.w);
        }
    }

    // ---- layer 4 + tp-reduction + ordered last-wins scatter (per m-tile) ----
#pragma unroll
    for (int t = 0; t < 2; t++) {
        float p0[6] = {0, 0, 0, 0, 0, 0}, p1[6] = {0, 0, 0, 0, 0, 0};
#pragma unroll
        for (int nt = 0; nt < 14; nt++) {
            int n0 = nt * 8 + tp * 2;
            float v0 = fmaxf(c3[t][nt][0], 0.f), v1 = fmaxf(c3[t][nt][1], 0.f);
            float v2 = fmaxf(c3[t][nt][2], 0.f), v3 = fmaxf(c3[t][nt][3], 0.f);
            if (n0 < 100) {
                const float *w = w4s + n0 * 6;
#pragma unroll
                for (int j = 0; j < 6; j++) {
                    p0[j] = fmaf(v0, w[j], p0[j]);
                    p1[j] = fmaf(v2, w[j], p1[j]);
                }
            }
            if (n0 + 1 < 100) {
                const float *w = w4s + (n0 + 1) * 6;
#pragma unroll
                for (int j = 0; j < 6; j++) {
                    p0[j] = fmaf(v1, w[j], p0[j]);
                    p1[j] = fmaf(v3, w[j], p1[j]);
                }
            }
        }
#pragma unroll
        for (int j = 0; j < 6; j++) {
            p0[j] += __shfl_xor_sync(0xffffffffu, p0[j], 1);
            p0[j] += __shfl_xor_sync(0xffffffffu, p0[j], 2);
            p1[j] += __shfl_xor_sync(0xffffffffu, p1[j], 1);
            p1[j] += __shfl_xor_sync(0xffffffffu, p1[j], 2);
        }
        if (tp == 0) {
            int mt = wid * 2 + t;
#pragma unroll
            for (int h = 0; h < 2; h++) {
                int s = mt * 16 + gid + h * 8;
                float *pp = h ? p1 : p0;
                if (s < nv) {
                    int meta = meta_s[s];
                    int row  = meta & 0xFFFF;
                    int ptr  = meta >> 16;
                    float *orow = out + (size_t)row * X_N;
                    int idx[6];
                    idx[0] = 0;
                    idx[1] = ptr;
                    idx[2] = min(max(ptr - GRID_S, 1), X_N - 1);
                    idx[3] = min(max(ptr + GRID_S, 1), X_N - 1);
                    idx[4] = min(max(ptr - 1, 1), X_N - 1);
                    idx[5] = min(max(ptr + 1, 1), X_N - 1);
                    // program order within one thread => last-wins like reference loop
#pragma unroll
                    for (int j = 0; j < 6; j++)
                        orow[idx[j]] = att_s[s * 6 + j] + (pp[j] + b4s[j]);
                }
            }
        }
    }
}

// ---- launcher ----
extern "C" void kernel_launch(void *const *d_in, const int *in_sizes, int n_in,
                              void *d_out, int out_size) {
    const float *x  = (const float *)d_in[0];
    const float *W1 = (const float *)d_in[1];
    const float *b1 = (const float *)d_in[2];
    const float *W2 = (const float *)d_in[3];
    const float *b2 = (const float *)d_in[4];
    const float *W3 = (const float *)d_in[5];
    const float *b3 = (const float *)d_in[6];
    const float *W4 = (const float *)d_in[7];
    const float *b4 = (const float *)d_in[8];
    const int   *act = (const int *)d_in[9];
    float *out = (float *)d_out;

    cudaFuncSetAttribute(mlp_kernel, cudaFuncAttributeMaxDynamicSharedMemorySize, SMEM_SZ);

    wprep_kernel<<<(134400 + 255) / 256, 256>>>(W2, W3);
    prep_kernel<<<B_N / 32, 1024>>>(x, act, out);
    // worst-case tile count: 256 + 1 + 1
    mlp_kernel<<<258, 256, SMEM_SZ>>>(W1, b1, b2, b3, W4, b4, out);
}

// round 9
// speedup vs baseline: 8.5124x; 1.1625x over previous
#include <cuda_runtime.h>
#include <cuda_bf16.h>
#include <cstdint>

#define B_N 65536
#define X_N 362
#define GRID_S 19

// layer2: D[.x400] = h1[.x112] @ W2t ; layer3: D[.x112] = h2[.x400] @ W3t
#define KT2 7     // layer2 k-tiles (112/16)
#define KT3 25    // layer3 k-tiles (400/16) == layer2 nt-pairs
#define NP3 7     // layer3 nt-pairs (14/2)

// ---- K2 dynamic smem layout (bytes) ----
#define WF2_OFF  0            // [kt3(25)][kt2(7)][lane(32)]{u32 x4} = 89600 B
#define WF3_OFF  89600        // [kt3(25)][p(7)][lane(32)]{u32 x4}   = 89600 B
#define ATT_OFF  179200       // 256*6 f32
#define META_OFF 185344       // 256 int
#define W1S_OFF  186368       // 600 f32
#define B1S_OFF  188768       // 100 f32
#define W4S_OFF  189168       // 600 f32
#define B2S_OFF  191568       // 400 f32
#define B3S_OFF  193168       // 100 f32
#define B4S_OFF  193568       // 6 f32
#define SMEM_SZ  193600

// ---- scratch (static device globals; no runtime allocation) ----
__device__ int      g_cnt[3];
__device__ int      g_meta[3 * B_N];
__device__ float    g_att[3 * B_N * 6];
__device__ uint32_t g_w2f[3 * KT3 * KT2 * 128];   // uint4-packed nt-pair B fragments
__device__ uint32_t g_w3f[3 * KT3 * NP3 * 128];

// ---- helpers ----
static __device__ __forceinline__ uint32_t cvt_bf16x2(float lo, float hi) {
    uint32_t r;
    asm("cvt.rn.bf16x2.f32 %0, %1, %2;" : "=r"(r) : "f"(hi), "f"(lo));   // low half = lo
    return r;
}
static __device__ __forceinline__ void mma16816(float *c, const uint32_t *a,
                                                uint32_t b0, uint32_t b1) {
    asm volatile(
        "mma.sync.aligned.m16n8k16.row.col.f32.bf16.bf16.f32 "
        "{%0,%1,%2,%3}, {%4,%5,%6,%7}, {%8,%9}, {%0,%1,%2,%3};"
        : "+f"(c[0]), "+f"(c[1]), "+f"(c[2]), "+f"(c[3])
        : "r"(a[0]), "r"(a[1]), "r"(a[2]), "r"(a[3]), "r"(b0), "r"(b1));
}

// ---- K0: build uint4-packed B-fragment images (zero-padded) + reset counters ----
__global__ void __launch_bounds__(256) wprep_kernel(const float *__restrict__ W2,
                                                    const float *__restrict__ W3) {
    if (blockIdx.x == 0 && threadIdx.x < 3) g_cnt[threadIdx.x] = 0;
    int idx = blockIdx.x * 256 + threadIdx.x;
    if (idx < 67200) {                       // 3 * 25*7*128
        int a = idx / 22400, r = idx % 22400;
        int kt3 = r / 896, r2 = r % 896;
        int kt2 = r2 / 128, r3 = r2 % 128;
        int lane = r3 >> 2, u = r3 & 3;
        int gid = lane >> 2, tp = lane & 3;
        int nt = 2 * kt3 + (u >> 1), breg = u & 1;
        int n = nt * 8 + gid;                 // < 400
        int k = kt2 * 16 + tp * 2 + breg * 8; // pad k>=100
        float v0 = (k < 100) ? W2[a * 40000 + k * 400 + n] : 0.f;
        float v1 = (k + 1 < 100) ? W2[a * 40000 + (k + 1) * 400 + n] : 0.f;
        g_w2f[idx] = cvt_bf16x2(v0, v1);
    } else if (idx < 134400) {               // 3 * 25*7*128
        int i2 = idx - 67200;
        int a = i2 / 22400, r = i2 % 22400;
        int kt3 = r / 896, r2 = r % 896;
        int p = r2 / 128, r3 = r2 % 128;
        int lane = r3 >> 2, u = r3 & 3;
        int gid = lane >> 2, tp = lane & 3;
        int nt3 = 2 * p + (u >> 1), breg = u & 1;
        int n = nt3 * 8 + gid;                // pad n>=100
        int k = kt3 * 16 + tp * 2 + breg * 8; // < 400
        float v0 = (n < 100) ? W3[a * 40000 + k * 100 + n] : 0.f;
        float v1 = (n < 100) ? W3[a * 40000 + (k + 1) * 100 + n] : 0.f;
        g_w3f[i2] = cvt_bf16x2(v0, v1);
    }
}

// ---- K1: linear uint4 copy + lean per-row argmax + gather + bucket ----
__global__ void __launch_bounds__(1024) prep_kernel(const float *__restrict__ x,
                                                    const int *__restrict__ act,
                                                    float *__restrict__ out) {
    __shared__ int   s_cnt[3], s_base[3];
    __shared__ int   s_a[32], s_slot[32], s_meta[32];
    __shared__ float s_att[32][6];

    int tid = threadIdx.x, lane = tid & 31, w = tid >> 5;
    if (tid < 3) s_cnt[tid] = 0;
    __syncthreads();

    // ---- phase A: linear 128-bit copy of this CTA's 32-row region ----
    // 32 rows * 1448 B = 46336 B = 2896 uint4, 16B-aligned per CTA.
    {
        size_t fbase = (size_t)blockIdx.x * 32 * X_N;
        const uint4 *xs = reinterpret_cast<const uint4 *>(x + fbase);
        uint4 *os = reinterpret_cast<uint4 *>(out + fbase);
        __stcs(&os[tid], xs[tid]);
        __stcs(&os[1024 + tid], xs[1024 + tid]);
        if (tid < 848) __stcs(&os[2048 + tid], xs[2048 + tid]);
    }

    // ---- phase B: warp-per-row argmax (values kept in regs; L1-hot) ----
    int row = blockIdx.x * 32 + w;
    const float2 *xr = reinterpret_cast<const float2 *>(x + (size_t)row * X_N);

    float2 vals[6];
    float bv = -3.4e38f;
#pragma unroll
    for (int j = 0; j < 6; j++) {
        int pi = lane + 32 * j;
        if (pi < 181) {                       // j<5 always; j==5 only lanes 0..20
            float2 v = xr[pi];
            vals[j] = v;
            bv = fmaxf(bv, fmaxf(v.x, v.y));
        }
    }
#pragma unroll
    for (int off = 16; off > 0; off >>= 1)
        bv = fmaxf(bv, __shfl_xor_sync(0xffffffffu, bv, off));
    // min global index matching bv (first-index tie policy, like jnp.argmax)
    int bi = 0x7fffffff;
#pragma unroll
    for (int j = 0; j < 6; j++) {
        int pi = lane + 32 * j;
        if (pi < 181) {
            if (vals[j].x == bv) bi = min(bi, 2 * pi);
            if (vals[j].y == bv) bi = min(bi, 2 * pi + 1);
        }
    }
#pragma unroll
    for (int off = 16; off > 0; off >>= 1)
        bi = min(bi, __shfl_xor_sync(0xffffffffu, bi, off));

    if (lane == 0) {
        int ptr = bi;
        int a   = act[row];
        const float *xp = x + (size_t)row * X_N;
        int il  = min(max(ptr - GRID_S, 1), X_N - 1);
        int ir  = min(max(ptr + GRID_S, 1), X_N - 1);
        int iu  = min(max(ptr - 1, 1), X_N - 1);
        int idn = min(max(ptr + 1, 1), X_N - 1);
        s_att[w][0] = xp[0];
        s_att[w][1] = bv;       // == xp[ptr]
        s_att[w][2] = xp[il];
        s_att[w][3] = xp[ir];
        s_att[w][4] = xp[iu];
        s_att[w][5] = xp[idn];
        s_meta[w] = row | (ptr << 16);
        s_a[w]    = a;
        s_slot[w] = atomicAdd(&s_cnt[a], 1);
    }
    __syncthreads();
    if (tid < 3) s_base[tid] = atomicAdd(&g_cnt[tid], s_cnt[tid]);
    __syncthreads();
    if (lane == 0) {
        int a = s_a[w];
        int g = s_base[a] + s_slot[w];
        g_meta[a * B_N + g] = s_meta[w];
        float *dst = &g_att[(size_t)(a * B_N + g) * 6];
#pragma unroll
        for (int j = 0; j < 6; j++) dst[j] = s_att[w][j];
    }
}

// ---- K2: fused mma MLP. 256 samples/CTA, 8 warps x 2 m-tiles, layers 2+3 fused ----
__global__ void __launch_bounds__(256, 1) mlp_kernel(
    const float *__restrict__ W1, const float *__restrict__ b1,
    const float *__restrict__ b2, const float *__restrict__ b3,
    const float *__restrict__ W4, const float *__restrict__ b4,
    float *__restrict__ out) {
    int c0n = g_cnt[0], c1n = g_cnt[1], c2n = g_cnt[2];
    int t0 = (c0n + 255) >> 8, t1 = (c1n + 255) >> 8, t2 = (c2n + 255) >> 8;
    int bid = blockIdx.x;
    int a, tile, cnt;
    if (bid < t0)                { a = 0; tile = bid;            cnt = c0n; }
    else if (bid < t0 + t1)      { a = 1; tile = bid - t0;       cnt = c1n; }
    else if (bid < t0 + t1 + t2) { a = 2; tile = bid - t0 - t1;  cnt = c2n; }
    else return;
    int base = tile * 256;
    int nv   = min(256, cnt - base);

    extern __shared__ char smem[];
    const uint4 *wf2 = reinterpret_cast<const uint4 *>(smem + WF2_OFF);
    const uint4 *wf3 = reinterpret_cast<const uint4 *>(smem + WF3_OFF);
    float *att_s = reinterpret_cast<float *>(smem + ATT_OFF);
    int   *meta_s = reinterpret_cast<int *>(smem + META_OFF);
    float *w1s = reinterpret_cast<float *>(smem + W1S_OFF);
    float *b1s = reinterpret_cast<float *>(smem + B1S_OFF);
    float *w4s = reinterpret_cast<float *>(smem + W4S_OFF);
    float *b2s = reinterpret_cast<float *>(smem + B2S_OFF);
    float *b3s = reinterpret_cast<float *>(smem + B3S_OFF);
    float *b4s = reinterpret_cast<float *>(smem + B4S_OFF);

    int tid = threadIdx.x, lane = tid & 31, wid = tid >> 5;
    int gid = lane >> 2, tp = lane & 3;

    // ---- phase 0: cooperative loads ----
    for (int t = tid; t < 1536; t += 256) {
        int s = t / 6;
        att_s[t] = (s < nv) ? g_att[(size_t)(a * B_N + base) * 6 + t] : 0.f;
    }
    if (tid < 256) meta_s[tid] = (tid < nv) ? g_meta[a * B_N + base + tid] : 0;
    for (int t = tid; t < 600; t += 256) { w1s[t] = W1[a * 600 + t]; w4s[t] = W4[a * 600 + t]; }
    if (tid < 100) { b1s[tid] = b1[a * 100 + tid]; b3s[tid] = b3[a * 100 + tid]; }
    for (int t = tid; t < 400; t += 256) b2s[t] = b2[a * 400 + t];
    if (tid < 6) b4s[tid] = b4[a * 6 + tid];
    {
        const uint4 *s2 = reinterpret_cast<const uint4 *>(g_w2f + a * 22400);
        uint4 *d2 = reinterpret_cast<uint4 *>(smem + WF2_OFF);
        for (int i = tid; i < 5600; i += 256) d2[i] = s2[i];
        const uint4 *s3 = reinterpret_cast<const uint4 *>(g_w3f + a * 22400);
        uint4 *d3 = reinterpret_cast<uint4 *>(smem + WF3_OFF);
        for (int i = tid; i < 5600; i += 256) d3[i] = s3[i];
    }
    __syncthreads();

    // ---- layer 1: h1 directly into A-fragments for both m-tiles ----
    uint32_t a2[2][KT2][4];
#pragma unroll
    for (int t = 0; t < 2; t++) {
        int mt = wid * 2 + t;
        int r0 = mt * 16 + gid, r1 = r0 + 8;
        float at0[6], at1[6];
#pragma unroll
        for (int j = 0; j < 6; j++) { at0[j] = att_s[r0 * 6 + j]; at1[j] = att_s[r1 * 6 + j]; }
#pragma unroll
        for (int kt = 0; kt < KT2; kt++) {
            float h0[4], h1v[4];
            int ks0 = kt * 16 + tp * 2;
#pragma unroll
            for (int q = 0; q < 4; q++) {
                int k = ks0 + (q >> 1) * 8 + (q & 1);
                float v0 = 0.f, v1 = 0.f;
                if (k < 100) {
                    float acc0 = b1s[k], acc1 = b1s[k];
#pragma unroll
                    for (int j = 0; j < 6; j++) {
                        float wv = w1s[j * 100 + k];
                        acc0 = fmaf(at0[j], wv, acc0);
                        acc1 = fmaf(at1[j], wv, acc1);
                    }
                    v0 = fmaxf(acc0, 0.f);
                    v1 = fmaxf(acc1, 0.f);
                }
                h0[q] = v0; h1v[q] = v1;
            }
            a2[t][kt][0] = cvt_bf16x2(h0[0], h0[1]);
            a2[t][kt][1] = cvt_bf16x2(h1v[0], h1v[1]);
            a2[t][kt][2] = cvt_bf16x2(h0[2], h0[3]);
            a2[t][kt][3] = cvt_bf16x2(h1v[2], h1v[3]);
        }
    }

    // ---- fused layers 2+3: per kt3, compute layer2 nt-pair then feed 14 layer3 mmas ----
    float c3[2][14][4];
#pragma unroll
    for (int t = 0; t < 2; t++)
#pragma unroll
        for (int nt = 0; nt < 14; nt++) {
            int n0 = nt * 8 + tp * 2;
            float bl = (n0 < 100) ? b3s[n0] : 0.f;
            float bh = (n0 + 1 < 100) ? b3s[n0 + 1] : 0.f;
            c3[t][nt][0] = bl; c3[t][nt][1] = bh; c3[t][nt][2] = bl; c3[t][nt][3] = bh;
        }

#pragma unroll 1
    for (int kt3 = 0; kt3 < KT3; kt3++) {
        float c2[2][2][4];
#pragma unroll
        for (int t = 0; t < 2; t++)
#pragma unroll
            for (int h = 0; h < 2; h++) {
                float2 bb = *reinterpret_cast<const float2 *>(b2s + (2 * kt3 + h) * 8 + tp * 2);
                c2[t][h][0] = bb.x; c2[t][h][1] = bb.y; c2[t][h][2] = bb.x; c2[t][h][3] = bb.y;
            }
#pragma unroll
        for (int kt2 = 0; kt2 < KT2; kt2++) {
            uint4 bf = wf2[(kt3 * KT2 + kt2) * 32 + lane];
            mma16816(c2[0][0], a2[0][kt2], bf.x, bf.y);
            mma16816(c2[0][1], a2[0][kt2], bf.z, bf.w);
            mma16816(c2[1][0], a2[1][kt2], bf.x, bf.y);
            mma16816(c2[1][1], a2[1][kt2], bf.z, bf.w);
        }
        uint32_t a3f[2][4];
#pragma unroll
        for (int t = 0; t < 2; t++) {
            a3f[t][0] = cvt_bf16x2(fmaxf(c2[t][0][0], 0.f), fmaxf(c2[t][0][1], 0.f));
            a3f[t][1] = cvt_bf16x2(fmaxf(c2[t][0][2], 0.f), fmaxf(c2[t][0][3], 0.f));
            a3f[t][2] = cvt_bf16x2(fmaxf(c2[t][1][0], 0.f), fmaxf(c2[t][1][1], 0.f));
            a3f[t][3] = cvt_bf16x2(fmaxf(c2[t][1][2], 0.f), fmaxf(c2[t][1][3], 0.f));
        }
#pragma unroll
        for (int p = 0; p < NP3; p++) {
            uint4 bf = wf3[(kt3 * NP3 + p) * 32 + lane];
            mma16816(c3[0][2 * p],     a3f[0], bf.x, bf.y);
            mma16816(c3[0][2 * p + 1], a3f[0], bf.z, bf.w);
            mma16816(c3[1][2 * p],     a3f[1], bf.x, bf.y);
            mma16816(c3[1][2 * p + 1], a3f[1], bf.z, bf.w);
        }
    }

    // ---- layer 4 + tp-reduction + ordered last-wins scatter (per m-tile) ----
#pragma unroll
    for (int t = 0; t < 2; t++) {
        float p0[6] = {0, 0, 0, 0, 0, 0}, p1[6] = {0, 0, 0, 0, 0, 0};
#pragma unroll
        for (int nt = 0; nt < 14; nt++) {
            int n0 = nt * 8 + tp * 2;
            float v0 = fmaxf(c3[t][nt][0], 0.f), v1 = fmaxf(c3[t][nt][1], 0.f);
            float v2 = fmaxf(c3[t][nt][2], 0.f), v3 = fmaxf(c3[t][nt][3], 0.f);
            if (n0 < 100) {
                const float *wv = w4s + n0 * 6;
#pragma unroll
                for (int j = 0; j < 6; j++) {
                    p0[j] = fmaf(v0, wv[j], p0[j]);
                    p1[j] = fmaf(v2, wv[j], p1[j]);
                }
            }
            if (n0 + 1 < 100) {
                const float *wv = w4s + (n0 + 1) * 6;
#pragma unroll
                for (int j = 0; j < 6; j++) {
                    p0[j] = fmaf(v1, wv[j], p0[j]);
                    p1[j] = fmaf(v3, wv[j], p1[j]);
                }
            }
        }
#pragma unroll
        for (int j = 0; j < 6; j++) {
            p0[j] += __shfl_xor_sync(0xffffffffu, p0[j], 1);
            p0[j] += __shfl_xor_sync(0xffffffffu, p0[j], 2);
            p1[j] += __shfl_xor_sync(0xffffffffu, p1[j], 1);
            p1[j] += __shfl_xor_sync(0xffffffffu, p1[j], 2);
        }
        if (tp == 0) {
            int mt = wid * 2 + t;
#pragma unroll
            for (int h = 0; h < 2; h++) {
                int s = mt * 16 + gid + h * 8;
                float *pp = h ? p1 : p0;
                if (s < nv) {
                    int meta = meta_s[s];
                    int row  = meta & 0xFFFF;
                    int ptr  = meta >> 16;
                    float *orow = out + (size_t)row * X_N;
                    int idx[6];
                    idx[0] = 0;
                    idx[1] = ptr;
                    idx[2] = min(max(ptr - GRID_S, 1), X_N - 1);
                    idx[3] = min(max(ptr + GRID_S, 1), X_N - 1);
                    idx[4] = min(max(ptr - 1, 1), X_N - 1);
                    idx[5] = min(max(ptr + 1, 1), X_N - 1);
                    // program order within one thread => last-wins like reference loop
#pragma unroll
                    for (int j = 0; j < 6; j++)
                        orow[idx[j]] = att_s[s * 6 + j] + (pp[j] + b4s[j]);
                }
            }
        }
    }
}

// ---- launcher ----
extern "C" void kernel_launch(void *const *d_in, const int *in_sizes, int n_in,
                              void *d_out, int out_size) {
    const float *x  = (const float *)d_in[0];
    const float *W1 = (const float *)d_in[1];
    const float *b1 = (const float *)d_in[2];
    const float *W2 = (const float *)d_in[3];
    const float *b2 = (const float *)d_in[4];
    const float *W3 = (const float *)d_in[5];
    const float *b3 = (const float *)d_in[6];
    const float *W4 = (const float *)d_in[7];
    const float *b4 = (const float *)d_in[8];
    const int   *act = (const int *)d_in[9];
    float *out = (float *)d_out;

    cudaFuncSetAttribute(mlp_kernel, cudaFuncAttributeMaxDynamicSharedMemorySize, SMEM_SZ);

    wprep_kernel<<<(134400 + 255) / 256, 256>>>(W2, W3);
    prep_kernel<<<B_N / 32, 1024>>>(x, act, out);
    // worst-case tile count: 256 + 1 + 1
    mlp_kernel<<<258, 256, SMEM_SZ>>>(W1, b1, b2, b3, W4, b4, out);
}